// round 12
// baseline (speedup 1.0000x reference)
#include <cuda_runtime.h>

// BambooBase fused Coulomb(Ewald) + D3-CSO dispersion edge kernel.
// R12: R10 base (best) + load-side shuffle transpose for dij, but with the
// long-latency chain (idx -> atom gather) issued FIRST so the coalesced
// dij loads + SHFL transpose execute entirely under the gather shadow.
// Ledger: 83 -> 77 L1 wavefronts/warp with no added front-path latency.

#define MAX_ATOMS 200064

__device__ float4 g_atom[MAX_ATOMS];

__device__ __forceinline__ float frcp(float x) { return __fdividef(1.0f, x); }

__global__ __launch_bounds__(512) void pack_atoms_kernel(
    const float* __restrict__ charge,
    const float* __restrict__ c6,
    const float* __restrict__ r0,
    int N)
{
    const float SQRT_ELE = 18.222615f;   // sqrt(332.0637)
    int t = blockIdx.x * blockDim.x + threadIdx.x;
    int base = 4 * t;
    if (base + 3 < N) {
        float4 q  = *(const float4*)(charge + base);
        float4 cc = *(const float4*)(c6 + base);
        float4 rr = *(const float4*)(r0 + base);
        g_atom[base + 0] = make_float4(q.x * SQRT_ELE, sqrtf(cc.x), 1.25f * rr.x, 0.f);
        g_atom[base + 1] = make_float4(q.y * SQRT_ELE, sqrtf(cc.y), 1.25f * rr.y, 0.f);
        g_atom[base + 2] = make_float4(q.z * SQRT_ELE, sqrtf(cc.z), 1.25f * rr.z, 0.f);
        g_atom[base + 3] = make_float4(q.w * SQRT_ELE, sqrtf(cc.w), 1.25f * rr.w, 0.f);
    } else {
        for (int i = base; i < N; ++i) {
            g_atom[i] = make_float4(charge[i] * SQRT_ELE, sqrtf(c6[i]), 1.25f * r0[i], 0.f);
        }
    }
}

// Forward transpose (for stores): V[3k+c] = component c of lane k.
__device__ __forceinline__ float gatherV(float v0, float v1, float v2, int j)
{
    int k = j / 3;              // source lane
    int c = j - 3 * k;          // source component
    float t0 = __shfl_sync(0xffffffffu, v0, k);
    float t1 = __shfl_sync(0xffffffffu, v1, k);
    float t2 = __shfl_sync(0xffffffffu, v2, k);
    return c == 0 ? t0 : (c == 1 ? t1 : t2);
}

// Inverse transpose (for loads): element j of the warp's 96-float window
// lives in register u[j>>5] of lane (j&31).
__device__ __forceinline__ float pickU(float u0, float u1, float u2, int j)
{
    int src = j & 31;
    int m   = j >> 5;
    float t0 = __shfl_sync(0xffffffffu, u0, src);
    float t1 = __shfl_sync(0xffffffffu, u1, src);
    float t2 = __shfl_sync(0xffffffffu, u2, src);
    return m == 0 ? t0 : (m == 1 ? t1 : t2);
}

__global__ __launch_bounds__(256) void bamboo_edge_kernel(
    const int* __restrict__ row,
    const int* __restrict__ col,
    const float* __restrict__ dij,
    float* __restrict__ out,
    int E)
{
    int i = blockIdx.x * blockDim.x + threadIdx.x;
    int lane = threadIdx.x & 31;
    int wbase = i - lane;                 // first edge of this warp
    bool full = (wbase + 31 < E);         // whole warp in range?
    bool act  = (i < E);

    const float EWALD_F    = 1.12837917f;
    const float EWALD_P    = 0.3275911f;
    const float A0 = 0.254829592f, A1 = -0.284496736f, A2 = 1.421413741f,
                A3 = -1.453152027f, A4 = 1.061405429f;
    const float COUL_R0    = 2.2f;
    const float INV_R0     = 1.0f / 2.2f;
    const float BETA_OVER_R0 = 18.7f / 2.2f;   // 8.5
    const float INV_BETA   = 1.0f / 18.7f;
    const float G_EWALD    = 0.3f;
    const float R6_SHIFT   = 8303.765625f;      // 4.5^6
    const float INV_CUT6   = 1.0e-6f;           // 1/10^6

    // ---- Phase A: long-latency chain first (idx -> gathers) ----
    int r = 0, c = 0;
    if (act) {
        r = __ldcs(row + i);
        c = __ldcs(col + i);
    }
    float4 pa = make_float4(0.f, 0.f, 1.f, 0.f);
    float4 pb = make_float4(0.f, 0.f, 1.f, 0.f);
    if (act) {
        pa = __ldg(&g_atom[r]);
        pb = __ldg(&g_atom[c]);
    }

    // ---- Phase B: dij coalesced loads + inverse shuffle transpose ----
    // (independent of Phase A; executes under the gather latency shadow)
    float dx, dy, dz;
    if (full) {
        const float* dbase = dij + 3 * wbase;
        float u0 = __ldcs(dbase + lane);
        float u1 = __ldcs(dbase + 32 + lane);
        float u2 = __ldcs(dbase + 64 + lane);
        int j = 3 * lane;
        dx = pickU(u0, u1, u2, j);
        dy = pickU(u0, u1, u2, j + 1);
        dz = pickU(u0, u1, u2, j + 2);
    } else if (act) {
        int i3 = 3 * i;
        dx = __ldcs(dij + i3 + 0);
        dy = __ldcs(dij + i3 + 1);
        dz = __ldcs(dij + i3 + 2);
    } else {
        dx = dy = dz = 1.0f;   // dummy, keeps inactive-lane math finite
    }

    float ecoul = 0.f, cfx = 0.f, cfy = 0.f, cfz = 0.f;
    float edisp = 0.f, dfx = 0.f, dfy = 0.f, dfz = 0.f;

    if (act) {
        float r2   = dx*dx + dy*dy + dz*dz;
        float rinv = rsqrtf(r2);
        float rij  = r2 * rinv;
        float rinv2 = rinv * rinv;

        // ---- Coulomb ----
        float prefactor = pa.x * pb.x * rinv;

        float x  = BETA_OVER_R0 * (rij - COUL_R0);
        float ex = __expf(x);
        float one_p_ex = 1.0f + ex;
        float inv_1pex = frcp(one_p_ex);
        float damp = ex * inv_1pex;
        float sp   = __logf(one_p_ex) * INV_BETA;
        float s    = rij * INV_R0 * frcp(1.0f + sp);

        ecoul = prefactor * s;
        float fcoul = prefactor * damp * s * s;

        float grij  = G_EWALD * rij;
        float expm2 = __expf(-grij * grij);
        float t     = frcp(1.0f + EWALD_P * grij);
        float erfc  = t * (A0 + t * (A1 + t * (A2 + t * (A3 + t * A4)))) * expm2;

        ecoul += prefactor * (erfc - 1.0f);
        fcoul += prefactor * (erfc + EWALD_F * grij * expm2 - 1.0f);

        float cscale = fcoul * rinv2;
        cfx = dx * cscale;
        cfy = dy * cscale;
        cfz = dz * cscale;

        // ---- Dispersion (D3-CSO) ----
        float c6ij = pa.y * pb.y;

        float r6pow = r2 * r2 * r2;
        float inv_r6 = frcp(r6pow + R6_SHIFT);

        float e   = __expf(rij - (pa.z + pb.z));
        float inv_1pe = frcp(1.0f + e);
        float cso = 0.85f + 0.82f * inv_1pe;

        float c6_inv_r6 = c6ij * inv_r6;
        edisp = c6ij * INV_CUT6 - c6_inv_r6 * cso;

        float r5 = r2 * r2 * rij;
        float fdisp = -6.0f * c6ij * r5 * inv_r6 * inv_r6 * cso
                      - c6_inv_r6 * (0.82f * e * inv_1pe * inv_1pe);

        float dscale = fdisp * rinv;
        dfx = dx * dscale;
        dfy = dy * dscale;
        dfz = dz * dscale;

        // scalar (already coalesced) stores
        __stcs(out + i, ecoul);
        __stcs(out + 4*E + i, edisp);
    }

    if (full) {
        // ---- coalesced transposed stores for coul_fij ----
        {
            float* base = out + E + 3 * wbase;
            float u0 = gatherV(cfx, cfy, cfz, lane);
            float u1 = gatherV(cfx, cfy, cfz, lane + 32);
            float u2 = gatherV(cfx, cfy, cfz, lane + 64);
            __stcs(base + lane,      u0);
            __stcs(base + lane + 32, u1);
            __stcs(base + lane + 64, u2);
        }
        // ---- coalesced transposed stores for disp_fij ----
        {
            float* base = out + 5*E + 3 * wbase;
            float u0 = gatherV(dfx, dfy, dfz, lane);
            float u1 = gatherV(dfx, dfy, dfz, lane + 32);
            float u2 = gatherV(dfx, dfy, dfz, lane + 64);
            __stcs(base + lane,      u0);
            __stcs(base + lane + 32, u1);
            __stcs(base + lane + 64, u2);
        }
    } else if (act) {
        // tail warp: plain per-edge stores
        int i3 = 3 * i;
        float* cf = out + E + i3;
        cf[0] = cfx; cf[1] = cfy; cf[2] = cfz;
        float* df = out + 5*E + i3;
        df[0] = dfx; df[1] = dfy; df[2] = dfz;
    }
}

extern "C" void kernel_launch(void* const* d_in, const int* in_sizes, int n_in,
                              void* d_out, int out_size)
{
    const int*   row    = (const int*)d_in[0];
    const int*   col    = (const int*)d_in[1];
    const float* dij    = (const float*)d_in[2];
    const float* charge = (const float*)d_in[3];
    const float* c6     = (const float*)d_in[4];
    const float* r0     = (const float*)d_in[5];
    float* out = (float*)d_out;

    int E = in_sizes[0];
    int N = in_sizes[3];

    int packThreads = (N + 3) / 4;
    pack_atoms_kernel<<<(packThreads + 511) / 512, 512>>>(charge, c6, r0, N);
    bamboo_edge_kernel<<<(E + 255) / 256, 256>>>(row, col, dij, out, E);
}

// round 13
// speedup vs baseline: 1.1693x; 1.1693x over previous
#include <cuda_runtime.h>

// BambooBase fused Coulomb(Ewald) + D3-CSO dispersion edge kernel.
// R13: exact R10 memory structure (scalar __ldcs streams, default-cached
// float4 atom gathers, shuffle-transposed coalesced fij stores, __stcs),
// with block size 512: 31 regs -> 4 CTAs/SM -> 64 warps = 100% occupancy
// (vs 87.5% at 256x7), improving gather-latency hiding.

#define MAX_ATOMS 200064

__device__ float4 g_atom[MAX_ATOMS];

__device__ __forceinline__ float frcp(float x) { return __fdividef(1.0f, x); }

__global__ __launch_bounds__(512) void pack_atoms_kernel(
    const float* __restrict__ charge,
    const float* __restrict__ c6,
    const float* __restrict__ r0,
    int N)
{
    const float SQRT_ELE = 18.222615f;   // sqrt(332.0637)
    int t = blockIdx.x * blockDim.x + threadIdx.x;
    int base = 4 * t;
    if (base + 3 < N) {
        float4 q  = *(const float4*)(charge + base);
        float4 cc = *(const float4*)(c6 + base);
        float4 rr = *(const float4*)(r0 + base);
        g_atom[base + 0] = make_float4(q.x * SQRT_ELE, sqrtf(cc.x), 1.25f * rr.x, 0.f);
        g_atom[base + 1] = make_float4(q.y * SQRT_ELE, sqrtf(cc.y), 1.25f * rr.y, 0.f);
        g_atom[base + 2] = make_float4(q.z * SQRT_ELE, sqrtf(cc.z), 1.25f * rr.z, 0.f);
        g_atom[base + 3] = make_float4(q.w * SQRT_ELE, sqrtf(cc.w), 1.25f * rr.w, 0.f);
    } else {
        for (int i = base; i < N; ++i) {
            g_atom[i] = make_float4(charge[i] * SQRT_ELE, sqrtf(c6[i]), 1.25f * r0[i], 0.f);
        }
    }
}

// Forward transpose (for stores): V[3k+c] = component c of lane k.
__device__ __forceinline__ float gatherV(float v0, float v1, float v2, int j)
{
    int k = j / 3;              // source lane
    int c = j - 3 * k;          // source component
    float t0 = __shfl_sync(0xffffffffu, v0, k);
    float t1 = __shfl_sync(0xffffffffu, v1, k);
    float t2 = __shfl_sync(0xffffffffu, v2, k);
    return c == 0 ? t0 : (c == 1 ? t1 : t2);
}

__global__ __launch_bounds__(512) void bamboo_edge_kernel(
    const int* __restrict__ row,
    const int* __restrict__ col,
    const float* __restrict__ dij,
    float* __restrict__ out,
    int E)
{
    int i = blockIdx.x * blockDim.x + threadIdx.x;
    int lane = threadIdx.x & 31;
    int wbase = i - lane;                 // first edge of this warp
    bool full = (wbase + 31 < E);         // whole warp in range?
    bool act  = (i < E);

    const float EWALD_F    = 1.12837917f;
    const float EWALD_P    = 0.3275911f;
    const float A0 = 0.254829592f, A1 = -0.284496736f, A2 = 1.421413741f,
                A3 = -1.453152027f, A4 = 1.061405429f;
    const float COUL_R0    = 2.2f;
    const float INV_R0     = 1.0f / 2.2f;
    const float BETA_OVER_R0 = 18.7f / 2.2f;   // 8.5
    const float INV_BETA   = 1.0f / 18.7f;
    const float G_EWALD    = 0.3f;
    const float R6_SHIFT   = 8303.765625f;      // 4.5^6
    const float INV_CUT6   = 1.0e-6f;           // 1/10^6

    float ecoul = 0.f, cfx = 0.f, cfy = 0.f, cfz = 0.f;
    float edisp = 0.f, dfx = 0.f, dfy = 0.f, dfz = 0.f;

    if (act) {
        // streaming (evict-first) loads: one-touch data, keep L1 for the atom table
        int r = __ldcs(row + i);
        int c = __ldcs(col + i);

        int i3 = 3 * i;
        float dx = __ldcs(dij + i3 + 0);
        float dy = __ldcs(dij + i3 + 1);
        float dz = __ldcs(dij + i3 + 2);

        // gathers: default caching (atom table is the only L1-resident data)
        float4 pa = __ldg(&g_atom[r]);
        float4 pb = __ldg(&g_atom[c]);

        float r2   = dx*dx + dy*dy + dz*dz;
        float rinv = rsqrtf(r2);
        float rij  = r2 * rinv;
        float rinv2 = rinv * rinv;

        // ---- Coulomb ----
        float prefactor = pa.x * pb.x * rinv;

        float x  = BETA_OVER_R0 * (rij - COUL_R0);
        float ex = __expf(x);
        float one_p_ex = 1.0f + ex;
        float inv_1pex = frcp(one_p_ex);
        float damp = ex * inv_1pex;
        float sp   = __logf(one_p_ex) * INV_BETA;
        float s    = rij * INV_R0 * frcp(1.0f + sp);

        ecoul = prefactor * s;
        float fcoul = prefactor * damp * s * s;

        float grij  = G_EWALD * rij;
        float expm2 = __expf(-grij * grij);
        float t     = frcp(1.0f + EWALD_P * grij);
        float erfc  = t * (A0 + t * (A1 + t * (A2 + t * (A3 + t * A4)))) * expm2;

        ecoul += prefactor * (erfc - 1.0f);
        fcoul += prefactor * (erfc + EWALD_F * grij * expm2 - 1.0f);

        float cscale = fcoul * rinv2;
        cfx = dx * cscale;
        cfy = dy * cscale;
        cfz = dz * cscale;

        // ---- Dispersion (D3-CSO) ----
        float c6ij = pa.y * pb.y;

        float r6pow = r2 * r2 * r2;
        float inv_r6 = frcp(r6pow + R6_SHIFT);

        float e   = __expf(rij - (pa.z + pb.z));
        float inv_1pe = frcp(1.0f + e);
        float cso = 0.85f + 0.82f * inv_1pe;

        float c6_inv_r6 = c6ij * inv_r6;
        edisp = c6ij * INV_CUT6 - c6_inv_r6 * cso;

        float r5 = r2 * r2 * rij;
        float fdisp = -6.0f * c6ij * r5 * inv_r6 * inv_r6 * cso
                      - c6_inv_r6 * (0.82f * e * inv_1pe * inv_1pe);

        float dscale = fdisp * rinv;
        dfx = dx * dscale;
        dfy = dy * dscale;
        dfz = dz * dscale;

        // scalar (already coalesced) stores
        __stcs(out + i, ecoul);
        __stcs(out + 4*E + i, edisp);
    }

    if (full) {
        // ---- coalesced transposed stores for coul_fij ----
        {
            float* base = out + E + 3 * wbase;
            float u0 = gatherV(cfx, cfy, cfz, lane);
            float u1 = gatherV(cfx, cfy, cfz, lane + 32);
            float u2 = gatherV(cfx, cfy, cfz, lane + 64);
            __stcs(base + lane,      u0);
            __stcs(base + lane + 32, u1);
            __stcs(base + lane + 64, u2);
        }
        // ---- coalesced transposed stores for disp_fij ----
        {
            float* base = out + 5*E + 3 * wbase;
            float u0 = gatherV(dfx, dfy, dfz, lane);
            float u1 = gatherV(dfx, dfy, dfz, lane + 32);
            float u2 = gatherV(dfx, dfy, dfz, lane + 64);
            __stcs(base + lane,      u0);
            __stcs(base + lane + 32, u1);
            __stcs(base + lane + 64, u2);
        }
    } else if (act) {
        // tail warp: plain per-edge stores
        int i3 = 3 * i;
        float* cf = out + E + i3;
        cf[0] = cfx; cf[1] = cfy; cf[2] = cfz;
        float* df = out + 5*E + i3;
        df[0] = dfx; df[1] = dfy; df[2] = dfz;
    }
}

extern "C" void kernel_launch(void* const* d_in, const int* in_sizes, int n_in,
                              void* d_out, int out_size)
{
    const int*   row    = (const int*)d_in[0];
    const int*   col    = (const int*)d_in[1];
    const float* dij    = (const float*)d_in[2];
    const float* charge = (const float*)d_in[3];
    const float* c6     = (const float*)d_in[4];
    const float* r0     = (const float*)d_in[5];
    float* out = (float*)d_out;

    int E = in_sizes[0];
    int N = in_sizes[3];

    int packThreads = (N + 3) / 4;
    pack_atoms_kernel<<<(packThreads + 511) / 512, 512>>>(charge, c6, r0, N);
    bamboo_edge_kernel<<<(E + 511) / 512, 512>>>(row, col, dij, out, E);
}